// round 1
// baseline (speedup 1.0000x reference)
#include <cuda_runtime.h>

#define B_  16
#define T_  2048
#define R_  256
#define NS_ 4

// -------- scratch (static device globals; allocation-free kernel_launch) ----
__device__ float g_qp [(size_t)B_ * T_ * R_];            //  33.5 MB
__device__ float g_kp [(size_t)B_ * T_ * R_];            //  33.5 MB
__device__ float g_vs [(size_t)NS_ * B_ * T_ * R_];      // 134 MB   layout [NS][B][T][R]
__device__ float g_attn[(size_t)B_ * T_ * T_];           // 268 MB
__device__ float g_proj[(size_t)B_ * NS_ * T_];          // layout [B][NS][T]
__device__ float g_bloss[B_];

// ---------------------------------------------------------------------------
// 128x128x8 SIMT SGEMM core. 256 threads, 8x8 per thread, float4 ld/st.
// TRANSB=true : B is [N,K] row-major (x @ W^T style)
// TRANSB=false: B is [K,N] row-major
// All dims used here are multiples of 128 (M) / 128 (N) / 8 (K): no bounds checks.
// ---------------------------------------------------------------------------
template <bool TRANSB>
__device__ __forceinline__ void sgemm128(const float* __restrict__ A, int lda,
                                         const float* __restrict__ Bp, int ldb,
                                         int m0, int n0, int K,
                                         float acc[8][8])
{
    __shared__ float As[8][128];
    __shared__ float Bs[8][128];
    const int tid  = threadIdx.x;
    const int ty   = tid >> 4, tx = tid & 15;
    const int aRow = tid >> 1;             // 0..127
    const int aCol = (tid & 1) << 2;       // 0 or 4
    const int bRowN = tid >> 5;            // 0..7
    const int bColN = (tid & 31) << 2;     // 0..124

    for (int k0 = 0; k0 < K; k0 += 8) {
        float4 av = *reinterpret_cast<const float4*>(A + (size_t)(m0 + aRow) * lda + k0 + aCol);
        As[aCol + 0][aRow] = av.x;
        As[aCol + 1][aRow] = av.y;
        As[aCol + 2][aRow] = av.z;
        As[aCol + 3][aRow] = av.w;
        if (TRANSB) {
            float4 bv = *reinterpret_cast<const float4*>(Bp + (size_t)(n0 + aRow) * ldb + k0 + aCol);
            Bs[aCol + 0][aRow] = bv.x;
            Bs[aCol + 1][aRow] = bv.y;
            Bs[aCol + 2][aRow] = bv.z;
            Bs[aCol + 3][aRow] = bv.w;
        } else {
            float4 bv = *reinterpret_cast<const float4*>(Bp + (size_t)(k0 + bRowN) * ldb + n0 + bColN);
            *reinterpret_cast<float4*>(&Bs[bRowN][bColN]) = bv;
        }
        __syncthreads();
#pragma unroll
        for (int kk = 0; kk < 8; kk++) {
            float ra[8], rb[8];
            *reinterpret_cast<float4*>(ra)     = *reinterpret_cast<const float4*>(&As[kk][ty * 8]);
            *reinterpret_cast<float4*>(ra + 4) = *reinterpret_cast<const float4*>(&As[kk][ty * 8 + 4]);
            *reinterpret_cast<float4*>(rb)     = *reinterpret_cast<const float4*>(&Bs[kk][tx * 8]);
            *reinterpret_cast<float4*>(rb + 4) = *reinterpret_cast<const float4*>(&Bs[kk][tx * 8 + 4]);
#pragma unroll
            for (int i = 0; i < 8; i++)
#pragma unroll
                for (int j = 0; j < 8; j++)
                    acc[i][j] += ra[i] * rb[j];
        }
        __syncthreads();
    }
}

// ---------------------------------------------------------------------------
// Projections: C = X @ W^T + bias.  dst: 0->g_qp, 1->g_kp, 2->g_vs[z]
// M = B_*T_, N = K = R_.  grid = (2, 256, 1 or NS_)
// ---------------------------------------------------------------------------
__global__ void __launch_bounds__(256) k_proj(const float* __restrict__ X,
                                              const float* __restrict__ W,
                                              const float* __restrict__ bias,
                                              int dst)
{
    const int z  = blockIdx.z;
    const float* Wz = W    + (dst == 2 ? (size_t)z * R_ * R_ : 0);
    const float* bz = bias + (dst == 2 ? (size_t)z * R_      : 0);
    float* C = (dst == 0) ? g_qp
             : (dst == 1) ? g_kp
                          : (g_vs + (size_t)z * B_ * T_ * R_);

    const int m0 = blockIdx.y * 128, n0 = blockIdx.x * 128;
    float acc[8][8] = {};
    sgemm128<true>(X, R_, Wz, R_, m0, n0, R_, acc);

    const int ty = threadIdx.x >> 4, tx = threadIdx.x & 15;
#pragma unroll
    for (int i = 0; i < 8; i++) {
        const int row = m0 + ty * 8 + i;
        float4 o0, o1;
        const int col = n0 + tx * 8;
        o0.x = acc[i][0] + bz[col + 0]; o0.y = acc[i][1] + bz[col + 1];
        o0.z = acc[i][2] + bz[col + 2]; o0.w = acc[i][3] + bz[col + 3];
        o1.x = acc[i][4] + bz[col + 4]; o1.y = acc[i][5] + bz[col + 5];
        o1.z = acc[i][6] + bz[col + 6]; o1.w = acc[i][7] + bz[col + 7];
        *reinterpret_cast<float4*>(C + (size_t)row * R_ + col)     = o0;
        *reinterpret_cast<float4*>(C + (size_t)row * R_ + col + 4) = o1;
    }
}

// ---------------------------------------------------------------------------
// score = tril(qp @ kp^T * scale), with score==0 -> -10000 quirk.
// Upper-triangle blocks are filled directly (no GEMM).
// grid = (16, 16, 16)
// ---------------------------------------------------------------------------
__global__ void __launch_bounds__(256) k_score()
{
    const int b  = blockIdx.z;
    const int bi = blockIdx.y, bj = blockIdx.x;
    const int m0 = bi * 128, n0 = bj * 128;
    float* C = g_attn + (size_t)b * T_ * T_;
    const int tid = threadIdx.x;

    if (bj > bi) {  // fully masked block
        const float4 f4 = make_float4(-1e4f, -1e4f, -1e4f, -1e4f);
        for (int idx = tid; idx < 128 * 32; idx += 256) {
            const int r = idx >> 5, c = (idx & 31) << 2;
            *reinterpret_cast<float4*>(C + (size_t)(m0 + r) * T_ + n0 + c) = f4;
        }
        return;
    }

    const float* qp = g_qp + (size_t)b * T_ * R_;
    const float* kp = g_kp + (size_t)b * T_ * R_;
    float acc[8][8] = {};
    sgemm128<true>(qp, R_, kp, R_, m0, n0, R_, acc);

    const int ty = tid >> 4, tx = tid & 15;
#pragma unroll
    for (int i = 0; i < 8; i++) {
        const int row = m0 + ty * 8 + i;
#pragma unroll
        for (int j = 0; j < 8; j++) {
            const int col = n0 + tx * 8 + j;
            const float v = acc[i][j] * 0.0625f;   // 1/sqrt(256)
            C[(size_t)row * T_ + col] = (col > row || v == 0.0f) ? -1e4f : v;
        }
    }
}

// ---------------------------------------------------------------------------
// Row softmax over T_=2048, one block per row, row held in registers.
// ---------------------------------------------------------------------------
__global__ void __launch_bounds__(256) k_softmax()
{
    __shared__ float red[256];
    const int row = blockIdx.x;
    float* p = g_attn + (size_t)row * T_;
    const int tid = threadIdx.x;

    float v[8];
    float mx = -3.4e38f;
#pragma unroll
    for (int i = 0; i < 8; i++) { v[i] = p[tid + i * 256]; mx = fmaxf(mx, v[i]); }
    red[tid] = mx; __syncthreads();
    for (int s = 128; s > 0; s >>= 1) {
        if (tid < s) red[tid] = fmaxf(red[tid], red[tid + s]);
        __syncthreads();
    }
    mx = red[0]; __syncthreads();

    float sum = 0.f;
#pragma unroll
    for (int i = 0; i < 8; i++) { v[i] = expf(v[i] - mx); sum += v[i]; }
    red[tid] = sum; __syncthreads();
    for (int s = 128; s > 0; s >>= 1) {
        if (tid < s) red[tid] += red[tid + s];
        __syncthreads();
    }
    const float inv = 1.0f / red[0];
#pragma unroll
    for (int i = 0; i < 8; i++) p[tid + i * 256] = v[i] * inv;
}

// ---------------------------------------------------------------------------
// out[b,n] = attn[b] @ vs[n,b].  attn is exactly 0 above diagonal
// (expf(-1e4 - mx) underflows to 0.0f), so truncate K to m0+128.
// grid = (2, 16, 64); z = n*B_ + b
// ---------------------------------------------------------------------------
__global__ void __launch_bounds__(256) k_av(float* __restrict__ out)
{
    const int z = blockIdx.z;
    const int n = z / B_, b = z % B_;
    const float* A = g_attn + (size_t)b * T_ * T_;
    const float* V = g_vs   + ((size_t)n * B_ + b) * T_ * R_;
    float* C = out + ((size_t)b * NS_ + n) * T_ * R_;

    const int m0 = blockIdx.y * 128, n0 = blockIdx.x * 128;
    const int Keff = m0 + 128;   // causal: zero contribution beyond this
    float acc[8][8] = {};
    sgemm128<false>(A, T_, V, R_, m0, n0, Keff, acc);

    const int ty = threadIdx.x >> 4, tx = threadIdx.x & 15;
#pragma unroll
    for (int i = 0; i < 8; i++) {
        const int row = m0 + ty * 8 + i;
        const int col = n0 + tx * 8;
        *reinterpret_cast<float4*>(C + (size_t)row * R_ + col)     = *reinterpret_cast<float4*>(&acc[i][0]);
        *reinterpret_cast<float4*>(C + (size_t)row * R_ + col + 4) = *reinterpret_cast<float4*>(&acc[i][4]);
    }
}

// ---------------------------------------------------------------------------
// proj[b,n,t] = vs[n,b,t,:] . wp + bp  — one warp per row.
// ---------------------------------------------------------------------------
__global__ void __launch_bounds__(256) k_projp(const float* __restrict__ wp,
                                               const float* __restrict__ bp)
{
    const int gw   = (blockIdx.x * blockDim.x + threadIdx.x) >> 5;   // 0..NS_*B_*T_-1
    const int lane = threadIdx.x & 31;
    const float* x = g_vs + (size_t)gw * R_;
    float s = 0.f;
#pragma unroll
    for (int r = lane; r < R_; r += 32) s += x[r] * wp[r];
#pragma unroll
    for (int o = 16; o > 0; o >>= 1) s += __shfl_down_sync(0xffffffffu, s, o);
    if (lane == 0) {
        const int n = gw / (B_ * T_);
        const int rem = gw % (B_ * T_);
        const int b = rem / T_, t = rem % T_;
        g_proj[((size_t)b * NS_ + n) * T_ + t] = s + bp[0];
    }
}

// ---------------------------------------------------------------------------
// Per-batch covariance abs-sum: bloss[b] = 0.5 * sum|cov(proj[b])|
// ---------------------------------------------------------------------------
__global__ void __launch_bounds__(256) k_cov()
{
    __shared__ float X[NS_][T_];   // 32 KB
    __shared__ float red[256];
    const int b = blockIdx.x, tid = threadIdx.x;

    for (int i = tid; i < NS_ * T_; i += 256)
        X[i / T_][i % T_] = g_proj[(size_t)b * NS_ * T_ + i];
    __syncthreads();

    float mean[NS_];
#pragma unroll
    for (int n = 0; n < NS_; n++) {
        float s = 0.f;
        for (int t = tid; t < T_; t += 256) s += X[n][t];
        red[tid] = s; __syncthreads();
        for (int st = 128; st > 0; st >>= 1) {
            if (tid < st) red[tid] += red[tid + st];
            __syncthreads();
        }
        mean[n] = red[0] / (float)T_;
        __syncthreads();
    }

    float total = 0.f;  // meaningful on tid 0 only
#pragma unroll
    for (int i = 0; i < NS_; i++)
#pragma unroll
        for (int j = 0; j <= i; j++) {
            float s = 0.f;
            for (int t = tid; t < T_; t += 256)
                s += (X[i][t] - mean[i]) * (X[j][t] - mean[j]);
            red[tid] = s; __syncthreads();
            for (int st = 128; st > 0; st >>= 1) {
                if (tid < st) red[tid] += red[tid + st];
                __syncthreads();
            }
            if (tid == 0) {
                const float c = red[0] / (float)(T_ - 1);
                total += (i == j ? 1.0f : 2.0f) * fabsf(c);
            }
            __syncthreads();
        }
    if (tid == 0) g_bloss[b] = 0.5f * total;
}

__global__ void k_final(float* __restrict__ out, long idx)
{
    float s = 0.f;
#pragma unroll
    for (int b = 0; b < B_; b++) s += g_bloss[b];
    out[idx] = s / (float)B_;
}

// ---------------------------------------------------------------------------
extern "C" void kernel_launch(void* const* d_in, const int* in_sizes, int n_in,
                              void* d_out, int out_size)
{
    (void)in_sizes; (void)n_in;
    const float* q  = (const float*)d_in[0];
    const float* k  = (const float*)d_in[1];
    const float* v  = (const float*)d_in[2];
    const float* wq = (const float*)d_in[3];
    const float* bq = (const float*)d_in[4];
    const float* wk = (const float*)d_in[5];
    const float* bk = (const float*)d_in[6];
    const float* wv = (const float*)d_in[7];
    const float* bv = (const float*)d_in[8];
    const float* wp = (const float*)d_in[9];
    const float* bp = (const float*)d_in[10];
    float* out = (float*)d_out;

    const dim3 blk(256);

    k_proj<<<dim3(R_ / 128, (B_ * T_) / 128, 1),  blk>>>(q, wq, bq, 0);
    k_proj<<<dim3(R_ / 128, (B_ * T_) / 128, 1),  blk>>>(k, wk, bk, 1);
    k_proj<<<dim3(R_ / 128, (B_ * T_) / 128, NS_), blk>>>(v, wv, bv, 2);

    k_score  <<<dim3(T_ / 128, T_ / 128, B_), blk>>>();
    k_softmax<<<B_ * T_, blk>>>();
    k_av     <<<dim3(R_ / 128, T_ / 128, B_ * NS_), blk>>>(out);

    k_projp<<<(NS_ * B_ * T_ * 32) / 256, blk>>>(wp, bp);
    k_cov  <<<B_, blk>>>();
    k_final<<<1, 1>>>(out, (long)out_size - 1);
}

// round 2
// speedup vs baseline: 1.0020x; 1.0020x over previous
#include <cuda_runtime.h>

#define B_  16
#define T_  2048
#define R_  256
#define NS_ 4

// -------- scratch (static device globals; allocation-free kernel_launch) ----
__device__ float g_qp [(size_t)B_ * T_ * R_];            //  33.5 MB
__device__ float g_kp [(size_t)B_ * T_ * R_];            //  33.5 MB
__device__ float g_vs [(size_t)NS_ * B_ * T_ * R_];      // 134 MB   layout [NS][B][T][R]
__device__ float g_attn[(size_t)B_ * T_ * T_];           // 268 MB
__device__ float g_proj[(size_t)B_ * NS_ * T_];          // layout [B][NS][T]
__device__ float g_bloss[B_];

// ---------------------------------------------------------------------------
// 128x128x8 SIMT SGEMM core. 256 threads, 8x8 per thread, float4 ld/st.
// TRANSB=true : B is [N,K] row-major (x @ W^T style)
// TRANSB=false: B is [K,N] row-major
// All dims used here are multiples of 128 (M) / 128 (N) / 8 (K): no bounds checks.
// ---------------------------------------------------------------------------
template <bool TRANSB>
__device__ __forceinline__ void sgemm128(const float* __restrict__ A, int lda,
                                         const float* __restrict__ Bp, int ldb,
                                         int m0, int n0, int K,
                                         float acc[8][8])
{
    __shared__ float As[8][128];
    __shared__ float Bs[8][128];
    const int tid  = threadIdx.x;
    const int ty   = tid >> 4, tx = tid & 15;
    const int aRow = tid >> 1;             // 0..127
    const int aCol = (tid & 1) << 2;       // 0 or 4
    const int bRowN = tid >> 5;            // 0..7
    const int bColN = (tid & 31) << 2;     // 0..124

    for (int k0 = 0; k0 < K; k0 += 8) {
        float4 av = *reinterpret_cast<const float4*>(A + (size_t)(m0 + aRow) * lda + k0 + aCol);
        As[aCol + 0][aRow] = av.x;
        As[aCol + 1][aRow] = av.y;
        As[aCol + 2][aRow] = av.z;
        As[aCol + 3][aRow] = av.w;
        if (TRANSB) {
            float4 bv = *reinterpret_cast<const float4*>(Bp + (size_t)(n0 + aRow) * ldb + k0 + aCol);
            Bs[aCol + 0][aRow] = bv.x;
            Bs[aCol + 1][aRow] = bv.y;
            Bs[aCol + 2][aRow] = bv.z;
            Bs[aCol + 3][aRow] = bv.w;
        } else {
            float4 bv = *reinterpret_cast<const float4*>(Bp + (size_t)(k0 + bRowN) * ldb + n0 + bColN);
            *reinterpret_cast<float4*>(&Bs[bRowN][bColN]) = bv;
        }
        __syncthreads();
#pragma unroll
        for (int kk = 0; kk < 8; kk++) {
            float ra[8], rb[8];
            *reinterpret_cast<float4*>(ra)     = *reinterpret_cast<const float4*>(&As[kk][ty * 8]);
            *reinterpret_cast<float4*>(ra + 4) = *reinterpret_cast<const float4*>(&As[kk][ty * 8 + 4]);
            *reinterpret_cast<float4*>(rb)     = *reinterpret_cast<const float4*>(&Bs[kk][tx * 8]);
            *reinterpret_cast<float4*>(rb + 4) = *reinterpret_cast<const float4*>(&Bs[kk][tx * 8 + 4]);
#pragma unroll
            for (int i = 0; i < 8; i++)
#pragma unroll
                for (int j = 0; j < 8; j++)
                    acc[i][j] += ra[i] * rb[j];
        }
        __syncthreads();
    }
}

// ---------------------------------------------------------------------------
// Projections: C = X @ W^T + bias.  dst: 0->g_qp, 1->g_kp, 2->g_vs[z]
// M = B_*T_, N = K = R_.  grid = (2, 256, 1 or NS_)
// ---------------------------------------------------------------------------
__global__ void __launch_bounds__(256) k_proj(const float* __restrict__ X,
                                              const float* __restrict__ W,
                                              const float* __restrict__ bias,
                                              int dst)
{
    const int z  = blockIdx.z;
    const float* Wz = W    + (dst == 2 ? (size_t)z * R_ * R_ : 0);
    const float* bz = bias + (dst == 2 ? (size_t)z * R_      : 0);
    float* C = (dst == 0) ? g_qp
             : (dst == 1) ? g_kp
                          : (g_vs + (size_t)z * B_ * T_ * R_);

    const int m0 = blockIdx.y * 128, n0 = blockIdx.x * 128;
    float acc[8][8] = {};
    sgemm128<true>(X, R_, Wz, R_, m0, n0, R_, acc);

    const int ty = threadIdx.x >> 4, tx = threadIdx.x & 15;
#pragma unroll
    for (int i = 0; i < 8; i++) {
        const int row = m0 + ty * 8 + i;
        float4 o0, o1;
        const int col = n0 + tx * 8;
        o0.x = acc[i][0] + bz[col + 0]; o0.y = acc[i][1] + bz[col + 1];
        o0.z = acc[i][2] + bz[col + 2]; o0.w = acc[i][3] + bz[col + 3];
        o1.x = acc[i][4] + bz[col + 4]; o1.y = acc[i][5] + bz[col + 5];
        o1.z = acc[i][6] + bz[col + 6]; o1.w = acc[i][7] + bz[col + 7];
        *reinterpret_cast<float4*>(C + (size_t)row * R_ + col)     = o0;
        *reinterpret_cast<float4*>(C + (size_t)row * R_ + col + 4) = o1;
    }
}

// ---------------------------------------------------------------------------
// score = tril(qp @ kp^T * scale), with score==0 -> -10000 quirk.
// Upper-triangle blocks are filled directly (no GEMM).
// grid = (16, 16, 16)
// ---------------------------------------------------------------------------
__global__ void __launch_bounds__(256) k_score()
{
    const int b  = blockIdx.z;
    const int bi = blockIdx.y, bj = blockIdx.x;
    const int m0 = bi * 128, n0 = bj * 128;
    float* C = g_attn + (size_t)b * T_ * T_;
    const int tid = threadIdx.x;

    if (bj > bi) {  // fully masked block
        const float4 f4 = make_float4(-1e4f, -1e4f, -1e4f, -1e4f);
        for (int idx = tid; idx < 128 * 32; idx += 256) {
            const int r = idx >> 5, c = (idx & 31) << 2;
            *reinterpret_cast<float4*>(C + (size_t)(m0 + r) * T_ + n0 + c) = f4;
        }
        return;
    }

    const float* qp = g_qp + (size_t)b * T_ * R_;
    const float* kp = g_kp + (size_t)b * T_ * R_;
    float acc[8][8] = {};
    sgemm128<true>(qp, R_, kp, R_, m0, n0, R_, acc);

    const int ty = tid >> 4, tx = tid & 15;
#pragma unroll
    for (int i = 0; i < 8; i++) {
        const int row = m0 + ty * 8 + i;
#pragma unroll
        for (int j = 0; j < 8; j++) {
            const int col = n0 + tx * 8 + j;
            const float v = acc[i][j] * 0.0625f;   // 1/sqrt(256)
            C[(size_t)row * T_ + col] = (col > row || v == 0.0f) ? -1e4f : v;
        }
    }
}

// ---------------------------------------------------------------------------
// Row softmax over T_=2048, one block per row, row held in registers.
// ---------------------------------------------------------------------------
__global__ void __launch_bounds__(256) k_softmax()
{
    __shared__ float red[256];
    const int row = blockIdx.x;
    float* p = g_attn + (size_t)row * T_;
    const int tid = threadIdx.x;

    float v[8];
    float mx = -3.4e38f;
#pragma unroll
    for (int i = 0; i < 8; i++) { v[i] = p[tid + i * 256]; mx = fmaxf(mx, v[i]); }
    red[tid] = mx; __syncthreads();
    for (int s = 128; s > 0; s >>= 1) {
        if (tid < s) red[tid] = fmaxf(red[tid], red[tid + s]);
        __syncthreads();
    }
    mx = red[0]; __syncthreads();

    float sum = 0.f;
#pragma unroll
    for (int i = 0; i < 8; i++) { v[i] = expf(v[i] - mx); sum += v[i]; }
    red[tid] = sum; __syncthreads();
    for (int s = 128; s > 0; s >>= 1) {
        if (tid < s) red[tid] += red[tid + s];
        __syncthreads();
    }
    const float inv = 1.0f / red[0];
#pragma unroll
    for (int i = 0; i < 8; i++) p[tid + i * 256] = v[i] * inv;
}

// ---------------------------------------------------------------------------
// out[b,n] = attn[b] @ vs[n,b].  attn is exactly 0 above diagonal
// (expf(-1e4 - mx) underflows to 0.0f), so truncate K to m0+128.
// grid = (2, 16, 64); z = n*B_ + b
// ---------------------------------------------------------------------------
__global__ void __launch_bounds__(256) k_av(float* __restrict__ out)
{
    const int z = blockIdx.z;
    const int n = z / B_, b = z % B_;
    const float* A = g_attn + (size_t)b * T_ * T_;
    const float* V = g_vs   + ((size_t)n * B_ + b) * T_ * R_;
    float* C = out + ((size_t)b * NS_ + n) * T_ * R_;

    const int m0 = blockIdx.y * 128, n0 = blockIdx.x * 128;
    const int Keff = m0 + 128;   // causal: zero contribution beyond this
    float acc[8][8] = {};
    sgemm128<false>(A, T_, V, R_, m0, n0, Keff, acc);

    const int ty = threadIdx.x >> 4, tx = threadIdx.x & 15;
#pragma unroll
    for (int i = 0; i < 8; i++) {
        const int row = m0 + ty * 8 + i;
        const int col = n0 + tx * 8;
        *reinterpret_cast<float4*>(C + (size_t)row * R_ + col)     = *reinterpret_cast<float4*>(&acc[i][0]);
        *reinterpret_cast<float4*>(C + (size_t)row * R_ + col + 4) = *reinterpret_cast<float4*>(&acc[i][4]);
    }
}

// ---------------------------------------------------------------------------
// proj[b,n,t] = vs[n,b,t,:] . wp + bp  — one warp per row.
// ---------------------------------------------------------------------------
__global__ void __launch_bounds__(256) k_projp(const float* __restrict__ wp,
                                               const float* __restrict__ bp)
{
    const int gw   = (blockIdx.x * blockDim.x + threadIdx.x) >> 5;   // 0..NS_*B_*T_-1
    const int lane = threadIdx.x & 31;
    const float* x = g_vs + (size_t)gw * R_;
    float s = 0.f;
#pragma unroll
    for (int r = lane; r < R_; r += 32) s += x[r] * wp[r];
#pragma unroll
    for (int o = 16; o > 0; o >>= 1) s += __shfl_down_sync(0xffffffffu, s, o);
    if (lane == 0) {
        const int n = gw / (B_ * T_);
        const int rem = gw % (B_ * T_);
        const int b = rem / T_, t = rem % T_;
        g_proj[((size_t)b * NS_ + n) * T_ + t] = s + bp[0];
    }
}

// ---------------------------------------------------------------------------
// Per-batch covariance abs-sum: bloss[b] = 0.5 * sum|cov(proj[b])|
// ---------------------------------------------------------------------------
__global__ void __launch_bounds__(256) k_cov()
{
    __shared__ float X[NS_][T_];   // 32 KB
    __shared__ float red[256];
    const int b = blockIdx.x, tid = threadIdx.x;

    for (int i = tid; i < NS_ * T_; i += 256)
        X[i / T_][i % T_] = g_proj[(size_t)b * NS_ * T_ + i];
    __syncthreads();

    float mean[NS_];
#pragma unroll
    for (int n = 0; n < NS_; n++) {
        float s = 0.f;
        for (int t = tid; t < T_; t += 256) s += X[n][t];
        red[tid] = s; __syncthreads();
        for (int st = 128; st > 0; st >>= 1) {
            if (tid < st) red[tid] += red[tid + st];
            __syncthreads();
        }
        mean[n] = red[0] / (float)T_;
        __syncthreads();
    }

    float total = 0.f;  // meaningful on tid 0 only
#pragma unroll
    for (int i = 0; i < NS_; i++)
#pragma unroll
        for (int j = 0; j <= i; j++) {
            float s = 0.f;
            for (int t = tid; t < T_; t += 256)
                s += (X[i][t] - mean[i]) * (X[j][t] - mean[j]);
            red[tid] = s; __syncthreads();
            for (int st = 128; st > 0; st >>= 1) {
                if (tid < st) red[tid] += red[tid + st];
                __syncthreads();
            }
            if (tid == 0) {
                const float c = red[0] / (float)(T_ - 1);
                total += (i == j ? 1.0f : 2.0f) * fabsf(c);
            }
            __syncthreads();
        }
    if (tid == 0) g_bloss[b] = 0.5f * total;
}

__global__ void k_final(float* __restrict__ out, long idx)
{
    float s = 0.f;
#pragma unroll
    for (int b = 0; b < B_; b++) s += g_bloss[b];
    out[idx] = s / (float)B_;
}

// ---------------------------------------------------------------------------
extern "C" void kernel_launch(void* const* d_in, const int* in_sizes, int n_in,
                              void* d_out, int out_size)
{
    (void)in_sizes; (void)n_in;
    const float* q  = (const float*)d_in[0];
    const float* k  = (const float*)d_in[1];
    const float* v  = (const float*)d_in[2];
    const float* wq = (const float*)d_in[3];
    const float* bq = (const float*)d_in[4];
    const float* wk = (const float*)d_in[5];
    const float* bk = (const float*)d_in[6];
    const float* wv = (const float*)d_in[7];
    const float* bv = (const float*)d_in[8];
    const float* wp = (const float*)d_in[9];
    const float* bp = (const float*)d_in[10];
    float* out = (float*)d_out;

    const dim3 blk(256);

    k_proj<<<dim3(R_ / 128, (B_ * T_) / 128, 1),  blk>>>(q, wq, bq, 0);
    k_proj<<<dim3(R_ / 128, (B_ * T_) / 128, 1),  blk>>>(k, wk, bk, 1);
    k_proj<<<dim3(R_ / 128, (B_ * T_) / 128, NS_), blk>>>(v, wv, bv, 2);

    k_score  <<<dim3(T_ / 128, T_ / 128, B_), blk>>>();
    k_softmax<<<B_ * T_, blk>>>();
    k_av     <<<dim3(R_ / 128, T_ / 128, B_ * NS_), blk>>>(out);

    k_projp<<<(NS_ * B_ * T_ * 32) / 256, blk>>>(wp, bp);
    k_cov  <<<B_, blk>>>();
    k_final<<<1, 1>>>(out, (long)out_size - 1);
}

// round 4
// speedup vs baseline: 2.4090x; 2.4041x over previous
#include <cuda_runtime.h>
#include <cuda_bf16.h>
#include <cstdint>

#define B_  16
#define T_  2048
#define R_  256
#define NS_ 4
#define BT_ (B_*T_)
typedef __nv_bfloat16 bf16;

// ----------------------------- device scratch ------------------------------
__device__ bf16 g_qh[(size_t)BT_*R_],  g_ql[(size_t)BT_*R_];
__device__ bf16 g_kh[(size_t)BT_*R_],  g_kl[(size_t)BT_*R_];
__device__ bf16 g_vh[(size_t)BT_*R_],  g_vl[(size_t)BT_*R_];
__device__ bf16 g_wqh[R_*R_], g_wql[R_*R_];
__device__ bf16 g_wkh[R_*R_], g_wkl[R_*R_];
__device__ bf16 g_wvh[NS_*R_*R_], g_wvl[NS_*R_*R_];
__device__ bf16 g_qph[(size_t)BT_*R_], g_qpl[(size_t)BT_*R_];
__device__ bf16 g_kph[(size_t)BT_*R_], g_kpl[(size_t)BT_*R_];
__device__ bf16 g_vth[(size_t)NS_*B_*R_*T_], g_vtl[(size_t)NS_*B_*R_*T_]; // [n][b][r][t]
__device__ float g_score[(size_t)B_*T_*T_];
__device__ bf16 g_ah[(size_t)B_*T_*T_], g_al[(size_t)B_*T_*T_];
__device__ float g_proj[B_*NS_*T_];   // [b][n][t]
__device__ float g_bloss[B_];

__device__ bf16* const g_hdst[6] = {g_qh,g_kh,g_vh,g_wqh,g_wkh,g_wvh};
__device__ bf16* const g_ldst[6] = {g_ql,g_kl,g_vl,g_wql,g_wkl,g_wvl};

// ------------------------------- PTX helpers -------------------------------
static __device__ __forceinline__ uint32_t smem_u32(const void* p) {
    return (uint32_t)__cvta_generic_to_shared(p);
}
static __device__ __forceinline__ void cp16(uint32_t d, const void* s) {
    asm volatile("cp.async.cg.shared.global [%0], [%1], 16;" :: "r"(d), "l"(s));
}
static __device__ __forceinline__ uint32_t swz(uint32_t o) { return o ^ ((o >> 3) & 0x70); }

static __device__ __forceinline__ void ldsm4(uint32_t* r, uint32_t addr) {
    asm volatile("ldmatrix.sync.aligned.m8n8.x4.shared.b16 {%0,%1,%2,%3}, [%4];"
                 : "=r"(r[0]), "=r"(r[1]), "=r"(r[2]), "=r"(r[3]) : "r"(addr));
}
static __device__ __forceinline__ void hmma(float* c, const uint32_t* a,
                                            uint32_t b0, uint32_t b1) {
    asm volatile(
        "mma.sync.aligned.m16n8k16.row.col.f32.bf16.bf16.f32 "
        "{%0,%1,%2,%3}, {%4,%5,%6,%7}, {%8,%9}, {%0,%1,%2,%3};"
        : "+f"(c[0]), "+f"(c[1]), "+f"(c[2]), "+f"(c[3])
        : "r"(a[0]), "r"(a[1]), "r"(a[2]), "r"(a[3]), "r"(b0), "r"(b1));
}

// smem: 2 stages x 64KB; each stage = Ah,Al,Bh,Bl tiles of 16KB
// (tile = 128 rows x 128B, SW128-swizzled).
#define STAGE_B 65536
#define SMEM_DYN 131072

// --------------------------- GEMM building blocks --------------------------
static __device__ __forceinline__ void load_chunk(
    uint32_t st, const bf16* __restrict__ Ah, const bf16* __restrict__ Al, long lda,
    const bf16* __restrict__ Bh, const bf16* __restrict__ Bl, long ldb, int k0, int tid)
{
    const int j = tid & 7, r0 = tid >> 3;
#pragma unroll
    for (int rr = 0; rr < 4; rr++) {
        const int row = r0 + rr * 32;
        const uint32_t d = swz((uint32_t)(row * 128 + j * 16));
        const long ao = (long)row * lda + k0 + j * 8;
        const long bo = (long)row * ldb + k0 + j * 8;
        cp16(st + d,         Ah + ao);
        cp16(st + 16384 + d, Al + ao);
        cp16(st + 32768 + d, Bh + bo);
        cp16(st + 49152 + d, Bl + bo);
    }
    asm volatile("cp.async.commit_group;" ::: "memory");
}

// Warp-tiled 128x128 GEMM with bf16x2 split (3 HMMA terms), acc in registers.
// acc[mt][nt][4]: warp tile 32(m) x 64(n); mOff = (wid&3)*32, nOff = (wid>>2)*64.
static __device__ __forceinline__ void gemm_core(
    char* sm, const bf16* Ah, const bf16* Al, long lda,
    const bf16* Bh, const bf16* Bl, long ldb, int NC, float acc[2][8][4])
{
    const int tid = threadIdx.x, lane = tid & 31, wid = tid >> 5;
    const int mOff = (wid & 3) * 32;
    const int nOff = (wid >> 2) * 64;
    const int aRow = lane & 15,                  aKb = (lane >> 4) << 4;
    const int bRow = (lane & 7) + ((lane >> 4) << 3), bKb = ((lane >> 3) & 1) << 4;
    const uint32_t sb = smem_u32(sm);

    load_chunk(sb, Ah, Al, lda, Bh, Bl, ldb, 0, tid);
    for (int c = 0; c < NC; c++) {
        const uint32_t st = sb + (uint32_t)(c & 1) * STAGE_B;
        if (c + 1 < NC) {
            load_chunk(sb + (uint32_t)((c + 1) & 1) * STAGE_B,
                       Ah, Al, lda, Bh, Bl, ldb, (c + 1) * 64, tid);
            asm volatile("cp.async.wait_group 1;" ::: "memory");
        } else {
            asm volatile("cp.async.wait_group 0;" ::: "memory");
        }
        __syncthreads();

#pragma unroll
        for (int ks = 0; ks < 4; ks++) {
            const int kb = ks * 32;
            uint32_t aH[2][4], aL[2][4], bH[4][4], bL[4][4];
#pragma unroll
            for (int mt = 0; mt < 2; mt++) {
                const uint32_t off = swz((uint32_t)((mOff + mt * 16 + aRow) * 128 + kb + aKb));
                ldsm4(aH[mt], st + off);
                ldsm4(aL[mt], st + 16384 + off);
            }
#pragma unroll
            for (int p = 0; p < 4; p++) {
                const uint32_t off = swz((uint32_t)((nOff + p * 16 + bRow) * 128 + kb + bKb));
                ldsm4(bH[p], st + 32768 + off);
                ldsm4(bL[p], st + 49152 + off);
            }
#pragma unroll
            for (int mt = 0; mt < 2; mt++)
#pragma unroll
                for (int nt = 0; nt < 8; nt++) {
                    const int p = nt >> 1, q = (nt & 1) << 1;
                    hmma(acc[mt][nt], aH[mt], bH[p][q], bH[p][q + 1]);
                    hmma(acc[mt][nt], aL[mt], bH[p][q], bH[p][q + 1]);
                    hmma(acc[mt][nt], aH[mt], bL[p][q], bL[p][q + 1]);
                }
        }
        __syncthreads();   // protect stage before it is overwritten
    }
}

// ------------------------------ split kernels ------------------------------
__global__ void __launch_bounds__(256) k_split(const float* __restrict__ x, int which, long n)
{
    bf16* __restrict__ h = g_hdst[which];
    bf16* __restrict__ l = g_ldst[which];
    long i = (long)blockIdx.x * blockDim.x + threadIdx.x;
    const long stride = (long)gridDim.x * blockDim.x;
    for (; i < n; i += stride) {
        const float v = x[i];
        const bf16 hi = __float2bfloat16(v);
        h[i] = hi;
        l[i] = __float2bfloat16(v - __bfloat162float(hi));
    }
}

// --------------------------- projection GEMMs ------------------------------
// which: 0=q->qp, 1=k->kp, 2=v->vsT (transposed epilogue, grid.z = NS_)
__global__ void __launch_bounds__(256) k_pgemm(int which, const float* __restrict__ bias)
{
    extern __shared__ char sm[];
    const int tid = threadIdx.x, lane = tid & 31, wid = tid >> 5;
    const int z = blockIdx.z;
    const int m0 = blockIdx.y * 128, n0 = blockIdx.x * 128;

    const bf16 *Xh, *Xl, *Wh, *Wl;
    bf16 *Oh, *Ol;
    if (which == 0)      { Xh=g_qh; Xl=g_ql; Wh=g_wqh; Wl=g_wql; Oh=g_qph; Ol=g_qpl; }
    else if (which == 1) { Xh=g_kh; Xl=g_kl; Wh=g_wkh; Wl=g_wkl; Oh=g_kph; Ol=g_kpl; }
    else { Xh=g_vh; Xl=g_vl; Wh=g_wvh+(size_t)z*R_*R_; Wl=g_wvl+(size_t)z*R_*R_; Oh=g_vth; Ol=g_vtl; }
    const float* bz = bias + (which == 2 ? (size_t)z * R_ : 0);

    float acc[2][8][4] = {};
    gemm_core(sm, Xh + (size_t)m0 * R_, Xl + (size_t)m0 * R_, R_,
                  Wh + (size_t)n0 * R_, Wl + (size_t)n0 * R_, R_, R_ / 64, acc);

    const int g = lane >> 2, tg = lane & 3;
    const int mOff = (wid & 3) * 32, nOff = (wid >> 2) * 64;

    if (which == 2) {
        // vsT[n][b][r][t]: r = col, t = global row
        const int b = m0 / T_, t0 = m0 % T_;
        const size_t base = ((size_t)z * B_ + b) * R_ * T_;
#pragma unroll
        for (int mt = 0; mt < 2; mt++)
#pragma unroll
            for (int nt = 0; nt < 8; nt++) {
                const int col = n0 + nOff + nt * 8 + 2 * tg;
#pragma unroll
                for (int h = 0; h < 2; h++) {
                    const int t = t0 + mOff + mt * 16 + g + h * 8;
#pragma unroll
                    for (int cc = 0; cc < 2; cc++) {
                        const int rg = col + cc;
                        const float v = acc[mt][nt][h * 2 + cc] + __ldg(bz + rg);
                        const bf16 hi = __float2bfloat16(v);
                        const size_t o = base + (size_t)rg * T_ + t;
                        Oh[o] = hi;
                        Ol[o] = __float2bfloat16(v - __bfloat162float(hi));
                    }
                }
            }
    } else {
#pragma unroll
        for (int mt = 0; mt < 2; mt++)
#pragma unroll
            for (int nt = 0; nt < 8; nt++) {
                const int col = n0 + nOff + nt * 8 + 2 * tg;
                const float b0 = __ldg(bz + col), b1 = __ldg(bz + col + 1);
#pragma unroll
                for (int h = 0; h < 2; h++) {
                    const int row = m0 + mOff + mt * 16 + g + h * 8;
                    const float v0 = acc[mt][nt][h * 2 + 0] + b0;
                    const float v1 = acc[mt][nt][h * 2 + 1] + b1;
                    const bf16 h0 = __float2bfloat16(v0), h1 = __float2bfloat16(v1);
                    __nv_bfloat162 ph; ph.x = h0; ph.y = h1;
                    __nv_bfloat162 pl;
                    pl.x = __float2bfloat16(v0 - __bfloat162float(h0));
                    pl.y = __float2bfloat16(v1 - __bfloat162float(h1));
                    *reinterpret_cast<__nv_bfloat162*>(Oh + (size_t)row * R_ + col) = ph;
                    *reinterpret_cast<__nv_bfloat162*>(Ol + (size_t)row * R_ + col) = pl;
                }
            }
    }
}

// ------------------------------- score GEMM --------------------------------
// grid (136, 1, B_): lower-triangular 128x128 tiles only.
__global__ void __launch_bounds__(256) k_sgemm()
{
    extern __shared__ char sm[];
    const int tid = threadIdx.x, lane = tid & 31, wid = tid >> 5;
    const int b = blockIdx.z;
    const int idx = blockIdx.x;
    int bi = (int)((sqrtf(8.0f * idx + 1.0f) - 1.0f) * 0.5f);
    while ((bi + 1) * (bi + 2) / 2 <= idx) ++bi;
    while (bi * (bi + 1) / 2 > idx) --bi;
    const int bj = idx - bi * (bi + 1) / 2;
    const int m0 = bi * 128, n0 = bj * 128;

    float acc[2][8][4] = {};
    gemm_core(sm, g_qph + ((size_t)b * T_ + m0) * R_, g_qpl + ((size_t)b * T_ + m0) * R_, R_,
                  g_kph + ((size_t)b * T_ + n0) * R_, g_kpl + ((size_t)b * T_ + n0) * R_, R_,
                  R_ / 64, acc);

    float* C = g_score + (size_t)b * T_ * T_;
    const int g = lane >> 2, tg = lane & 3;
    const int mOff = (wid & 3) * 32, nOff = (wid >> 2) * 64;
#pragma unroll
    for (int mt = 0; mt < 2; mt++)
#pragma unroll
        for (int nt = 0; nt < 8; nt++) {
            const int gc = n0 + nOff + nt * 8 + 2 * tg;
#pragma unroll
            for (int h = 0; h < 2; h++) {
                const int gr = m0 + mOff + mt * 16 + g + h * 8;
                float v0 = acc[mt][nt][h * 2 + 0] * 0.0625f;
                float v1 = acc[mt][nt][h * 2 + 1] * 0.0625f;
                if (gc + 0 > gr || v0 == 0.0f) v0 = -1e4f;
                if (gc + 1 > gr || v1 == 0.0f) v1 = -1e4f;
                *reinterpret_cast<float2*>(C + (size_t)gr * T_ + gc) = make_float2(v0, v1);
            }
        }
}

// ------------------- softmax (fp32 in, split bf16 attn out) ----------------
__global__ void __launch_bounds__(256) k_softmax()
{
    __shared__ float red[256];
    const int gr = blockIdx.x;             // b*T_ + r
    const int r = gr & (T_ - 1);
    const int Ceil = (r & ~127) + 128;     // written score extent for this row
    const float* p = g_score + (size_t)gr * T_;
    bf16* ph = g_ah + (size_t)gr * T_;
    bf16* pl = g_al + (size_t)gr * T_;
    const int tid = threadIdx.x;

    float v[8];
    float mx = -3.4e38f;
#pragma unroll
    for (int i = 0; i < 8; i++) {
        const int c = tid + i * 256;
        v[i] = (c < Ceil) ? p[c] : -3.4e38f;
        mx = fmaxf(mx, v[i]);
    }
    red[tid] = mx; __syncthreads();
    for (int s = 128; s > 0; s >>= 1) {
        if (tid < s) red[tid] = fmaxf(red[tid], red[tid + s]);
        __syncthreads();
    }
    mx = red[0]; __syncthreads();

    float sum = 0.f;
#pragma unroll
    for (int i = 0; i < 8; i++) {
        const int c = tid + i * 256;
        if (c < Ceil) { v[i] = expf(v[i] - mx); sum += v[i]; } else v[i] = 0.f;
    }
    red[tid] = sum; __syncthreads();
    for (int s = 128; s > 0; s >>= 1) {
        if (tid < s) red[tid] += red[tid + s];
        __syncthreads();
    }
    const float inv = 1.0f / red[0];
#pragma unroll
    for (int i = 0; i < 8; i++) {
        const int c = tid + i * 256;
        if (c < Ceil) {
            const float a = v[i] * inv;
            const bf16 hi = __float2bfloat16(a);
            ph[c] = hi;
            pl[c] = __float2bfloat16(a - __bfloat162float(hi));
        }
    }
}

// --------------------------------- AV GEMM ---------------------------------
// grid (2, 16, 64): n0=bx*128 (r), m0=by*128 (t); z: n=z>>4, b=z&15
__global__ void __launch_bounds__(256) k_avgemm(float* __restrict__ out)
{
    extern __shared__ char sm[];
    const int tid = threadIdx.x, lane = tid & 31, wid = tid >> 5;
    const int z = blockIdx.z, n = z >> 4, b = z & 15;
    const int m0 = blockIdx.y * 128, n0 = blockIdx.x * 128;
    const int NC = blockIdx.y * 2 + 2;     // causal: attn==0 beyond m0+128

    float acc[2][8][4] = {};
    gemm_core(sm, g_ah + ((size_t)b * T_ + m0) * T_, g_al + ((size_t)b * T_ + m0) * T_, T_,
                  g_vth + (((size_t)n * B_ + b) * R_ + n0) * T_,
                  g_vtl + (((size_t)n * B_ + b) * R_ + n0) * T_, T_, NC, acc);

    float* C = out + ((size_t)b * NS_ + n) * T_ * R_;
    const int g = lane >> 2, tg = lane & 3;
    const int mOff = (wid & 3) * 32, nOff = (wid >> 2) * 64;
#pragma unroll
    for (int mt = 0; mt < 2; mt++)
#pragma unroll
        for (int nt = 0; nt < 8; nt++) {
            const int gc = n0 + nOff + nt * 8 + 2 * tg;
#pragma unroll
            for (int h = 0; h < 2; h++) {
                const int gr = m0 + mOff + mt * 16 + g + h * 8;
                *reinterpret_cast<float2*>(C + (size_t)gr * R_ + gc) =
                    make_float2(acc[mt][nt][h * 2 + 0], acc[mt][nt][h * 2 + 1]);
            }
        }
}

// --------------------------- proj / cov / final ----------------------------
__global__ void __launch_bounds__(256) k_projp(const float* __restrict__ wp,
                                               const float* __restrict__ bp)
{
    const int z = blockIdx.x, n = z >> 4, b = z & 15;
    const bf16* vh = g_vth + (size_t)z * R_ * T_;
    const bf16* vl = g_vtl + (size_t)z * R_ * T_;
    const int tid = threadIdx.x;
    float acc[8] = {};
    for (int r = 0; r < R_; r++) {
        const float w = __ldg(wp + r);
        const bf16* rh = vh + (size_t)r * T_;
        const bf16* rl = vl + (size_t)r * T_;
#pragma unroll
        for (int i = 0; i < 8; i++) {
            const int t = tid + i * 256;
            acc[i] += (__bfloat162float(rh[t]) + __bfloat162float(rl[t])) * w;
        }
    }
    const float bpv = __ldg(bp);
#pragma unroll
    for (int i = 0; i < 8; i++)
        g_proj[((size_t)b * NS_ + n) * T_ + tid + i * 256] = acc[i] + bpv;
}

__global__ void __launch_bounds__(256) k_cov()
{
    __shared__ float X[NS_][T_];
    __shared__ float red[256];
    const int b = blockIdx.x, tid = threadIdx.x;
    for (int i = tid; i < NS_ * T_; i += 256)
        X[i / T_][i % T_] = g_proj[(size_t)b * NS_ * T_ + i];
    __syncthreads();

    float mean[NS_];
#pragma unroll
    for (int n = 0; n < NS_; n++) {
        float s = 0.f;
        for (int t = tid; t < T_; t += 256) s += X[n][t];
        red[tid] = s; __syncthreads();
        for (int st = 128; st > 0; st >>= 1) {
            if (tid < st) red[tid] += red[tid + st];
            __syncthreads();
        }
        mean[n] = red[0] / (float)T_;
        __syncthreads();
    }

    float total = 0.f;
#pragma unroll
    for (int i = 0; i < NS_; i++)
#pragma unroll
        for (int j = 0; j <= i; j++) {
            float s = 0.f;
            for (int t = tid; t < T_; t += 256)
                s += (X[i][t] - mean[i]) * (X[j][t] - mean[j]);
            red[tid] = s; __syncthreads();
            for (int st = 128; st > 0; st >>= 1) {
                if (tid < st) red[tid] += red[tid + st];
                __syncthreads();
            }
            if (tid == 0) {
                const float c = red[0] / (float)(T_ - 1);
                total += (i == j ? 1.0f : 2.0f) * fabsf(c);
            }
            __syncthreads();
        }
    if (tid == 0) g_bloss[b] = 0.5f * total;
}

__global__ void k_final(float* __restrict__ out, long idx)
{
    float s = 0.f;
#pragma unroll
    for (int b = 0; b < B_; b++) s += g_bloss[b];
    out[idx] = s / (float)B_;
}

// ---------------------------------------------------------------------------
extern "C" void kernel_launch(void* const* d_in, const int* in_sizes, int n_in,
                              void* d_out, int out_size)
{
    (void)in_sizes; (void)n_in;
    const float* q  = (const float*)d_in[0];
    const float* k  = (const float*)d_in[1];
    const float* v  = (const float*)d_in[2];
    const float* wq = (const float*)d_in[3];
    const float* bq = (const float*)d_in[4];
    const float* wk = (const float*)d_in[5];
    const float* bk = (const float*)d_in[6];
    const float* wv = (const float*)d_in[7];
    const float* bv = (const float*)d_in[8];
    const float* wp = (const float*)d_in[9];
    const float* bp = (const float*)d_in[10];
    float* out = (float*)d_out;

    static bool attr_set = false;
    if (!attr_set) {
        cudaFuncSetAttribute(k_pgemm,  cudaFuncAttributeMaxDynamicSharedMemorySize, SMEM_DYN);
        cudaFuncSetAttribute(k_sgemm,  cudaFuncAttributeMaxDynamicSharedMemorySize, SMEM_DYN);
        cudaFuncSetAttribute(k_avgemm, cudaFuncAttributeMaxDynamicSharedMemorySize, SMEM_DYN);
        attr_set = true;
    }

    const dim3 blk(256);
    k_split<<<2048, blk>>>(q,  0, (long)BT_ * R_);
    k_split<<<2048, blk>>>(k,  1, (long)BT_ * R_);
    k_split<<<2048, blk>>>(v,  2, (long)BT_ * R_);
    k_split<<<64,   blk>>>(wq, 3, (long)R_ * R_);
    k_split<<<64,   blk>>>(wk, 4, (long)R_ * R_);
    k_split<<<256,  blk>>>(wv, 5, (long)NS_ * R_ * R_);

    k_pgemm<<<dim3(2, BT_ / 128, 1),   blk, SMEM_DYN>>>(0, bq);
    k_pgemm<<<dim3(2, BT_ / 128, 1),   blk, SMEM_DYN>>>(1, bk);
    k_pgemm<<<dim3(2, BT_ / 128, NS_), blk, SMEM_DYN>>>(2, bv);

    k_sgemm<<<dim3(136, 1, B_), blk, SMEM_DYN>>>();
    k_softmax<<<B_ * T_, blk>>>();
    k_avgemm<<<dim3(2, T_ / 128, NS_ * B_), blk, SMEM_DYN>>>(out);

    k_projp<<<NS_ * B_, blk>>>(wp, bp);
    k_cov<<<B_, blk>>>();
    k_final<<<1, 1>>>(out, (long)out_size - 1);
}